// round 1
// baseline (speedup 1.0000x reference)
#include <cuda_runtime.h>
#include <cstdint>
#include <cstddef>

#define S_LEN 2048
#define BATCH 32
#define EMB   512
#define HID   256
#define G3    768
#define M_ROWS (S_LEN * BATCH)              // 65536
#define OUT0  ((size_t)S_LEN * BATCH * 512) // offset of hidden in d_out

typedef unsigned long long u64;

// ---------------- scratch (static device allocations; no cudaMalloc) -------
__device__ float    gi_buf[(size_t)2 * M_ROWS * G3];   // ~402 MB: gi for both dirs
__device__ float    hbuf[2][2 * BATCH * HID];          // double-buffered h state
__device__ unsigned g_cnt[16];
__device__ unsigned g_phase[16];

// ---------------- packed f32x2 helpers ------------------------------------
__device__ __forceinline__ u64 fma2(u64 a, u64 b, u64 c) {
    u64 d;
    asm("fma.rn.f32x2 %0, %1, %2, %3;" : "=l"(d) : "l"(a), "l"(b), "l"(c));
    return d;
}
__device__ __forceinline__ u64 pack2(float x, float y) {
    u64 r;
    asm("mov.b64 %0, {%1, %2};" : "=l"(r) : "f"(x), "f"(y));
    return r;
}
__device__ __forceinline__ float2 unpack2(u64 v) {
    float2 f;
    asm("mov.b64 {%0, %1}, %2;" : "=f"(f.x), "=f"(f.y) : "l"(v));
    return f;
}

// ---------------- init: reset barrier + h state every replay ---------------
__global__ void init_kernel() {
    int t = blockIdx.x * blockDim.x + threadIdx.x;
    if (t < 16) { g_cnt[t] = 0; g_phase[t] = 0; }
    float* hb = &hbuf[0][0];
    for (int i = t; i < 2 * 2 * BATCH * HID; i += gridDim.x * blockDim.x)
        hb[i] = 0.f;
}

// ---------------- gi GEMM: gi[d][s*B+b][g] = x[s][b][:] . w_ih[g][:] + b_ih[g]
#define BM 128
#define BN 64
#define BK 16

__global__ __launch_bounds__(256, 2) void gi_gemm(
    const float* __restrict__ x,
    const float* __restrict__ wf, const float* __restrict__ bf,
    const float* __restrict__ wb, const float* __restrict__ bb)
{
    __shared__ float As[BK][BM];
    __shared__ float Ws[BK][BN];

    const int d  = blockIdx.z;
    const float* __restrict__ w  = d ? wb : wf;
    const float* __restrict__ bi = d ? bb : bf;
    const int m0 = blockIdx.y * BM;
    const int g0 = blockIdx.x * BN;
    const int tid = threadIdx.x;

    // staging-load indices
    const int am = tid >> 1;          // 0..127
    const int ak = (tid & 1) * 8;     // 0 or 8
    const int wn = tid >> 2;          // 0..63
    const int wk = (tid & 3) * 4;     // 0,4,8,12

    // micro-tile indices
    const int tx = tid & 15;          // n-tile (4 cols)
    const int ty = tid >> 4;          // m-tile (8 rows)

    u64 acc[8][2];
#pragma unroll
    for (int i = 0; i < 8; i++) { acc[i][0] = 0ull; acc[i][1] = 0ull; }

    // prologue: stage k=0 tile
    float4 a0r = *(const float4*)&x[(size_t)(m0 + am) * EMB + ak];
    float4 a1r = *(const float4*)&x[(size_t)(m0 + am) * EMB + ak + 4];
    float4 w0r = *(const float4*)&w[(size_t)(g0 + wn) * EMB + wk];

    for (int kt = 0; kt < EMB; kt += BK) {
        // regs -> smem (transposed)
        As[ak + 0][am] = a0r.x; As[ak + 1][am] = a0r.y;
        As[ak + 2][am] = a0r.z; As[ak + 3][am] = a0r.w;
        As[ak + 4][am] = a1r.x; As[ak + 5][am] = a1r.y;
        As[ak + 6][am] = a1r.z; As[ak + 7][am] = a1r.w;
        Ws[wk + 0][wn] = w0r.x; Ws[wk + 1][wn] = w0r.y;
        Ws[wk + 2][wn] = w0r.z; Ws[wk + 3][wn] = w0r.w;
        __syncthreads();

        // prefetch next tile into regs (hidden under compute)
        if (kt + BK < EMB) {
            a0r = *(const float4*)&x[(size_t)(m0 + am) * EMB + (kt + BK) + ak];
            a1r = *(const float4*)&x[(size_t)(m0 + am) * EMB + (kt + BK) + ak + 4];
            w0r = *(const float4*)&w[(size_t)(g0 + wn) * EMB + (kt + BK) + wk];
        }

#pragma unroll
        for (int k = 0; k < BK; k++) {
            float a[8];
            *(float4*)&a[0] = *(const float4*)&As[k][ty * 8];
            *(float4*)&a[4] = *(const float4*)&As[k][ty * 8 + 4];
            float4 wv = *(const float4*)&Ws[k][tx * 4];
            u64 wlo = pack2(wv.x, wv.y);
            u64 whi = pack2(wv.z, wv.w);
#pragma unroll
            for (int i = 0; i < 8; i++) {
                u64 ad = pack2(a[i], a[i]);
                acc[i][0] = fma2(ad, wlo, acc[i][0]);
                acc[i][1] = fma2(ad, whi, acc[i][1]);
            }
        }
        __syncthreads();
    }

    // epilogue: add bias, store
    const int m = m0 + ty * 8;
    const int g = g0 + tx * 4;
    const size_t base = (size_t)d * M_ROWS * G3;
    const float b0 = bi[g], b1 = bi[g + 1], b2 = bi[g + 2], b3 = bi[g + 3];
#pragma unroll
    for (int i = 0; i < 8; i++) {
        float2 lo = unpack2(acc[i][0]);
        float2 hi = unpack2(acc[i][1]);
        float4 o;
        o.x = lo.x + b0; o.y = lo.y + b1; o.z = hi.x + b2; o.w = hi.y + b3;
        *(float4*)&gi_buf[base + (size_t)(m + i) * G3 + g] = o;
    }
}

// ---------------- GRU scan -------------------------------------------------
// 128 blocks = 2 dirs x 8 batch-groups (4 batches) x 8 j-chunks (32 h-dims).
// 384 threads: t = kslice*96 + (gate*32 + jj). Each thread pins 64 W_hh
// floats in registers for the whole scan. h broadcast from shared.
__global__ __launch_bounds__(384, 1) void gru_scan(
    const float* __restrict__ whh_f, const float* __restrict__ bhh_f,
    const float* __restrict__ whh_b, const float* __restrict__ bhh_b,
    float* __restrict__ out)
{
    __shared__ __align__(16) float  h_sh[4 * HID];   // 4 batches x 256
    __shared__ __align__(16) float4 psum4[4 * 96];   // [kslice][row_local]

    const int bx  = blockIdx.x;
    const int d   = bx >> 6;
    const int rem = bx & 63;
    const int bg  = rem >> 3;       // batch group 0..7
    const int jc  = rem & 7;        // j-chunk 0..7
    const int j0  = jc * 32;
    const int grp = d * 8 + bg;

    const float* __restrict__ whh = d ? whh_b : whh_f;
    const float* __restrict__ bhh = d ? bhh_b : bhh_f;

    const int t    = threadIdx.x;
    const int ks   = t / 96;        // k-slice 0..3 (uniform per warp: 96 = 3*32)
    const int rl   = t % 96;        // gate*32 + jj
    const int gate = rl >> 5;
    const int jj   = rl & 31;
    const int rowg = gate * 256 + j0 + jj;

    // pin weight slice in registers (64 floats = 32 packed pairs)
    u64 w2[32];
    {
        const u64* wp = (const u64*)(whh + (size_t)rowg * HID + ks * 64);
#pragma unroll
        for (int i = 0; i < 32; i++) w2[i] = wp[i];
    }

    // gate-thread identity (t < 128): one (jj, b) output each
    const int gjj   = t >> 2;
    const int gb    = t & 3;
    const int bglob = bg * 4 + gb;
    float bh0 = 0.f, bh1 = 0.f, bh2 = 0.f;
    if (t < 128) {
        bh0 = bhh[j0 + gjj];
        bh1 = bhh[256 + j0 + gjj];
        bh2 = bhh[512 + j0 + gjj];
    }

    for (int step = 0; step < S_LEN; step++) {
        const int sidx = d ? (S_LEN - 1 - step) : step;
        const float* __restrict__ hrd = &hbuf[step & 1][d * BATCH * HID];
        float*       __restrict__ hwr = &hbuf[(step + 1) & 1][d * BATCH * HID];

        // stage h (L2-fresh reads; other SMs wrote it last step)
        for (int idx = t; idx < 4 * HID; idx += 384) {
            int b = idx >> 8, k = idx & 255;
            h_sh[idx] = __ldcg(&hrd[(bg * 4 + b) * HID + k]);
        }

        // issue gi loads early; consumed ~1k cycles later (latency hidden)
        float gi0 = 0.f, gi1 = 0.f, gi2 = 0.f;
        if (t < 128) {
            const float* gp = gi_buf +
                ((size_t)d * M_ROWS + (size_t)sidx * BATCH + bglob) * G3;
            gi0 = gp[j0 + gjj];
            gi1 = gp[256 + j0 + gjj];
            gi2 = gp[512 + j0 + gjj];
        }
        __syncthreads();

        // matvec: 4 batches x 32 packed-FMA, h loads are warp-uniform broadcast
        {
            u64 a0 = 0ull, a1 = 0ull, a2 = 0ull, a3 = 0ull;
            const u64* h0 = (const u64*)(h_sh + 0 * HID + ks * 64);
            const u64* h1 = (const u64*)(h_sh + 1 * HID + ks * 64);
            const u64* h2 = (const u64*)(h_sh + 2 * HID + ks * 64);
            const u64* h3 = (const u64*)(h_sh + 3 * HID + ks * 64);
#pragma unroll
            for (int i = 0; i < 32; i++) {
                a0 = fma2(w2[i], h0[i], a0);
                a1 = fma2(w2[i], h1[i], a1);
                a2 = fma2(w2[i], h2[i], a2);
                a3 = fma2(w2[i], h3[i], a3);
            }
            float2 f0 = unpack2(a0), f1 = unpack2(a1);
            float2 f2 = unpack2(a2), f3 = unpack2(a3);
            float4 p;
            p.x = f0.x + f0.y; p.y = f1.x + f1.y;
            p.z = f2.x + f2.y; p.w = f3.x + f3.y;
            psum4[ks * 96 + rl] = p;
        }
        __syncthreads();

        // gates + h update (128 threads)
        if (t < 128) {
            const float* pf = (const float*)psum4;
            float ghr = bh0, ghz = bh1, ghn = bh2;
#pragma unroll
            for (int k2 = 0; k2 < 4; k2++) {
                ghr += pf[(k2 * 96 +      gjj) * 4 + gb];
                ghz += pf[(k2 * 96 + 32 + gjj) * 4 + gb];
                ghn += pf[(k2 * 96 + 64 + gjj) * 4 + gb];
            }
            float hprev = h_sh[gb * HID + j0 + gjj];
            float r = 1.f / (1.f + expf(-(gi0 + ghr)));
            float z = 1.f / (1.f + expf(-(gi1 + ghz)));
            float n = tanhf(gi2 + r * ghn);
            float hy = n + z * (hprev - n);

            __stcg(&hwr[bglob * HID + j0 + gjj], hy);
            out[((size_t)sidx * BATCH + bglob) * 512 + d * HID + j0 + gjj] = hy;
            if (step == S_LEN - 1)
                out[OUT0 + (size_t)(d * BATCH + bglob) * HID + j0 + gjj] = hy;
        }
        __syncthreads();

        // 8-block group barrier (monotonic phase; state reset by init_kernel)
        if (t == 0) {
            __threadfence();
            unsigned a = atomicAdd(&g_cnt[grp], 1);
            if (a == 7u) {
                atomicExch(&g_cnt[grp], 0u);
                __threadfence();
                atomicExch(&g_phase[grp], (unsigned)(step + 1));
            } else {
                while (atomicAdd(&g_phase[grp], 0u) < (unsigned)(step + 1)) { }
            }
        }
        __syncthreads();
    }
}

// ---------------- launch ---------------------------------------------------
extern "C" void kernel_launch(void* const* d_in, const int* in_sizes, int n_in,
                              void* d_out, int out_size)
{
    const float* x      = (const float*)d_in[0];
    const float* w_ih_f = (const float*)d_in[1];
    const float* w_hh_f = (const float*)d_in[2];
    const float* b_ih_f = (const float*)d_in[3];
    const float* b_hh_f = (const float*)d_in[4];
    const float* w_ih_b = (const float*)d_in[5];
    const float* w_hh_b = (const float*)d_in[6];
    const float* b_ih_b = (const float*)d_in[7];
    const float* b_hh_b = (const float*)d_in[8];
    float* out = (float*)d_out;

    init_kernel<<<32, 256>>>();

    dim3 gg(G3 / BN, M_ROWS / BM, 2);   // (12, 512, 2)
    gi_gemm<<<gg, 256>>>(x, w_ih_f, b_ih_f, w_ih_b, b_ih_b);

    gru_scan<<<128, 384>>>(w_hh_f, b_hh_f, w_hh_b, b_hh_b, out);
}

// round 2
// speedup vs baseline: 1.0647x; 1.0647x over previous
#include <cuda_runtime.h>
#include <cstdint>
#include <cstddef>

#define S_LEN 2048
#define BATCH 32
#define EMB   512
#define HID   256
#define G3    768
#define M_ROWS (S_LEN * BATCH)              // 65536
#define OUT0  ((size_t)S_LEN * BATCH * 512) // offset of hidden in d_out

typedef unsigned long long u64;

// ---------------- scratch (static device allocation; no cudaMalloc) --------
__device__ float gi_buf[(size_t)2 * M_ROWS * G3];   // ~402 MB: gi for both dirs

// ---------------- packed f32x2 helpers ------------------------------------
__device__ __forceinline__ u64 fma2(u64 a, u64 b, u64 c) {
    u64 d;
    asm("fma.rn.f32x2 %0, %1, %2, %3;" : "=l"(d) : "l"(a), "l"(b), "l"(c));
    return d;
}
__device__ __forceinline__ u64 pack2(float x, float y) {
    u64 r;
    asm("mov.b64 %0, {%1, %2};" : "=l"(r) : "f"(x), "f"(y));
    return r;
}
__device__ __forceinline__ float2 unpack2(u64 v) {
    float2 f;
    asm("mov.b64 {%0, %1}, %2;" : "=f"(f.x), "=f"(f.y) : "l"(v));
    return f;
}
__device__ __forceinline__ uint32_t smem_u32(const void* p) {
    uint32_t a;
    asm("{ .reg .u64 t; cvta.to.shared.u64 t, %1; cvt.u32.u64 %0, t; }"
        : "=r"(a) : "l"(p));
    return a;
}

// ---------------- gi GEMM: gi[d][s*B+b][g] = x[s][b][:].w_ih[g][:] + b_ih[g]
// 128x128 block tile, BK=16, 256 threads, 8x8 micro-tile, f32x2 accumulators.
#define BM 128
#define BN 128
#define BK 16

__global__ __launch_bounds__(256, 2) void gi_gemm(
    const float* __restrict__ x,
    const float* __restrict__ wf, const float* __restrict__ bf,
    const float* __restrict__ wb, const float* __restrict__ bb)
{
    __shared__ float As[BK][BM];
    __shared__ float Ws[BK][BN];

    const int d  = blockIdx.z;
    const float* __restrict__ w  = d ? wb : wf;
    const float* __restrict__ bi = d ? bb : bf;
    const int m0 = blockIdx.y * BM;
    const int g0 = blockIdx.x * BN;
    const int tid = threadIdx.x;

    // staging: each thread loads 8 A floats + 8 W floats per tile
    const int lr = tid >> 1;          // row 0..127
    const int lk = (tid & 1) * 8;     // k offset 0 or 8

    // micro-tile: 8 n (tx) x 8 m (ty)
    const int tx = tid & 15;
    const int ty = tid >> 4;

    u64 acc[4][8];
#pragma unroll
    for (int i = 0; i < 4; i++)
#pragma unroll
        for (int j = 0; j < 8; j++) acc[i][j] = 0ull;

    const float* xp = &x[(size_t)(m0 + lr) * EMB + lk];
    const float* wp = &w[(size_t)(g0 + lr) * EMB + lk];

    float4 a0r = *(const float4*)(xp);
    float4 a1r = *(const float4*)(xp + 4);
    float4 w0r = *(const float4*)(wp);
    float4 w1r = *(const float4*)(wp + 4);

    for (int kt = 0; kt < EMB; kt += BK) {
        As[lk + 0][lr] = a0r.x; As[lk + 1][lr] = a0r.y;
        As[lk + 2][lr] = a0r.z; As[lk + 3][lr] = a0r.w;
        As[lk + 4][lr] = a1r.x; As[lk + 5][lr] = a1r.y;
        As[lk + 6][lr] = a1r.z; As[lk + 7][lr] = a1r.w;
        Ws[lk + 0][lr] = w0r.x; Ws[lk + 1][lr] = w0r.y;
        Ws[lk + 2][lr] = w0r.z; Ws[lk + 3][lr] = w0r.w;
        Ws[lk + 4][lr] = w1r.x; Ws[lk + 5][lr] = w1r.y;
        Ws[lk + 6][lr] = w1r.z; Ws[lk + 7][lr] = w1r.w;
        __syncthreads();

        if (kt + BK < EMB) {
            a0r = *(const float4*)(xp + kt + BK);
            a1r = *(const float4*)(xp + kt + BK + 4);
            w0r = *(const float4*)(wp + kt + BK);
            w1r = *(const float4*)(wp + kt + BK + 4);
        }

#pragma unroll
        for (int k = 0; k < BK; k++) {
            u64 am[4];
#pragma unroll
            for (int i = 0; i < 4; i++)
                am[i] = *(const u64*)&As[k][ty * 8 + i * 2];
            float4 v0 = *(const float4*)&Ws[k][tx * 8];
            float4 v1 = *(const float4*)&Ws[k][tx * 8 + 4];
            u64 wd[8];
            wd[0] = pack2(v0.x, v0.x); wd[1] = pack2(v0.y, v0.y);
            wd[2] = pack2(v0.z, v0.z); wd[3] = pack2(v0.w, v0.w);
            wd[4] = pack2(v1.x, v1.x); wd[5] = pack2(v1.y, v1.y);
            wd[6] = pack2(v1.z, v1.z); wd[7] = pack2(v1.w, v1.w);
#pragma unroll
            for (int i = 0; i < 4; i++)
#pragma unroll
                for (int j = 0; j < 8; j++)
                    acc[i][j] = fma2(am[i], wd[j], acc[i][j]);
        }
        __syncthreads();
    }

    // epilogue: bias + store. acc[i][j] = (out[m0+ty*8+2i][g], out[..+2i+1][g])
    const int gcol = g0 + tx * 8;
    const size_t base = (size_t)d * M_ROWS * G3;
    float bv[8];
#pragma unroll
    for (int j = 0; j < 8; j++) bv[j] = bi[gcol + j];

#pragma unroll
    for (int i = 0; i < 4; i++) {
        const int m = m0 + ty * 8 + i * 2;
        float o0[8], o1[8];
#pragma unroll
        for (int j = 0; j < 8; j++) {
            float2 f = unpack2(acc[i][j]);
            o0[j] = f.x + bv[j];
            o1[j] = f.y + bv[j];
        }
        *(float4*)&gi_buf[base + (size_t)(m + 0) * G3 + gcol]     = *(float4*)&o0[0];
        *(float4*)&gi_buf[base + (size_t)(m + 0) * G3 + gcol + 4] = *(float4*)&o0[4];
        *(float4*)&gi_buf[base + (size_t)(m + 1) * G3 + gcol]     = *(float4*)&o1[0];
        *(float4*)&gi_buf[base + (size_t)(m + 1) * G3 + gcol + 4] = *(float4*)&o1[4];
    }
}

// ---------------- GRU scan with 8-CTA clusters + DSMEM h-exchange ----------
// 128 blocks = 16 clusters of 8. Cluster = (dir, batch-group of 4 batches);
// rank within cluster = j-chunk (32 h-dims -> 96 gate rows).
// 384 threads: t = kslice*96 + gate*32 + jj. Each thread pins 64 W_hh floats
// in registers for all 2048 steps. h double-buffered in shared; new h pushed
// to all 8 cluster CTAs via st.shared::cluster; one barrier.cluster per step.
#define CLUSTER_SYNC() do { \
    asm volatile("barrier.cluster.arrive.aligned;" ::: "memory"); \
    asm volatile("barrier.cluster.wait.aligned;"   ::: "memory"); \
} while (0)

__global__ __launch_bounds__(384, 1) __cluster_dims__(8, 1, 1)
void gru_scan(
    const float* __restrict__ whh_f, const float* __restrict__ bhh_f,
    const float* __restrict__ whh_b, const float* __restrict__ bhh_b,
    float* __restrict__ out)
{
    __shared__ __align__(16) float  h_sh[2][4 * HID];  // double-buffered h
    __shared__ __align__(16) float4 psum4[4 * 96];     // [kslice][row_local]

    const int bx  = blockIdx.x;
    const int jc  = bx & 7;         // cluster rank = j-chunk
    const int grp = bx >> 3;
    const int bg  = grp & 7;        // batch group 0..7
    const int d   = grp >> 3;       // direction
    const int j0  = jc * 32;

    const float* __restrict__ whh = d ? whh_b : whh_f;
    const float* __restrict__ bhh = d ? bhh_b : bhh_f;

    const int t    = threadIdx.x;
    const int ks   = t / 96;        // k-slice 0..3 (warp-uniform: 96 = 3*32)
    const int rl   = t % 96;        // gate*32 + jj
    const int gate = rl >> 5;
    const int jj   = rl & 31;
    const int rowg = gate * 256 + j0 + jj;

    // pin weight slice in registers (64 floats = 32 packed pairs)
    u64 w2[32];
    {
        const u64* wpt = (const u64*)(whh + (size_t)rowg * HID + ks * 64);
#pragma unroll
        for (int i = 0; i < 32; i++) w2[i] = wpt[i];
    }

    // gate-thread identity (t < 128): one (jj, batch) output each
    const int gjj   = t >> 2;
    const int gb    = t & 3;
    const int bglob = bg * 4 + gb;
    float bh0 = 0.f, bh1 = 0.f, bh2 = 0.f;
    uint32_t remote[8];
    if (t < 128) {
        bh0 = bhh[j0 + gjj];
        bh1 = bhh[256 + j0 + gjj];
        bh2 = bhh[512 + j0 + gjj];
        uint32_t base = smem_u32(&h_sh[0][0]);
#pragma unroll
        for (int r = 0; r < 8; r++)
            asm("mapa.shared::cluster.u32 %0, %1, %2;"
                : "=r"(remote[r]) : "r"(base), "r"(r));
    }
    const uint32_t elem_off = (uint32_t)((gb * HID + j0 + gjj) * 4);

    // h = 0 in read buffer 0 (each block only ever reads its own h_sh)
    for (int idx = t; idx < 4 * HID; idx += 384) h_sh[0][idx] = 0.f;
    __syncthreads();

    for (int step = 0; step < S_LEN; step++) {
        const int rb = step & 1;
        const int nb = rb ^ 1;
        const int sidx = d ? (S_LEN - 1 - step) : step;

        // issue gi loads early (consumed after the matvec)
        float gi0 = 0.f, gi1 = 0.f, gi2 = 0.f;
        if (t < 128) {
            const float* gp = gi_buf +
                ((size_t)d * M_ROWS + (size_t)sidx * BATCH + bglob) * G3;
            gi0 = gp[j0 + gjj];
            gi1 = gp[256 + j0 + gjj];
            gi2 = gp[512 + j0 + gjj];
        }

        // matvec: 4 batches x 32 packed-FMA; h reads are warp-uniform LDS
        {
            u64 a0 = 0ull, a1 = 0ull, a2 = 0ull, a3 = 0ull;
            const u64* h0 = (const u64*)(h_sh[rb] + 0 * HID + ks * 64);
            const u64* h1 = (const u64*)(h_sh[rb] + 1 * HID + ks * 64);
            const u64* h2 = (const u64*)(h_sh[rb] + 2 * HID + ks * 64);
            const u64* h3 = (const u64*)(h_sh[rb] + 3 * HID + ks * 64);
#pragma unroll
            for (int i = 0; i < 32; i++) {
                a0 = fma2(w2[i], h0[i], a0);
                a1 = fma2(w2[i], h1[i], a1);
                a2 = fma2(w2[i], h2[i], a2);
                a3 = fma2(w2[i], h3[i], a3);
            }
            float2 f0 = unpack2(a0), f1 = unpack2(a1);
            float2 f2 = unpack2(a2), f3 = unpack2(a3);
            float4 p;
            p.x = f0.x + f0.y; p.y = f1.x + f1.y;
            p.z = f2.x + f2.y; p.w = f3.x + f3.y;
            psum4[ks * 96 + rl] = p;
        }
        __syncthreads();

        // gates + h update + DSMEM broadcast (128 threads)
        if (t < 128) {
            const float* pf = (const float*)psum4;
            float ghr = bh0, ghz = bh1, ghn = bh2;
#pragma unroll
            for (int k2 = 0; k2 < 4; k2++) {
                ghr += pf[(k2 * 96 +      gjj) * 4 + gb];
                ghz += pf[(k2 * 96 + 32 + gjj) * 4 + gb];
                ghn += pf[(k2 * 96 + 64 + gjj) * 4 + gb];
            }
            float hprev = h_sh[rb][gb * HID + j0 + gjj];
            float r = 1.f / (1.f + expf(-(gi0 + ghr)));
            float z = 1.f / (1.f + expf(-(gi1 + ghz)));
            float n = tanhf(gi2 + r * ghn);
            float hy = n + z * (hprev - n);

            // push hy into next-buffer h of all 8 cluster CTAs (incl. self)
            const uint32_t off = (uint32_t)(nb * 4 * HID * 4) + elem_off;
#pragma unroll
            for (int r8 = 0; r8 < 8; r8++)
                asm volatile("st.shared::cluster.f32 [%0], %1;"
                             :: "r"(remote[r8] + off), "f"(hy) : "memory");

            out[((size_t)sidx * BATCH + bglob) * 512 + d * HID + j0 + gjj] = hy;
            if (step == S_LEN - 1)
                out[OUT0 + (size_t)(d * BATCH + bglob) * HID + j0 + gjj] = hy;
        }

        // release DSMEM stores + acquire peers' stores; also reuses psum4
        CLUSTER_SYNC();
    }
}

// ---------------- launch ---------------------------------------------------
extern "C" void kernel_launch(void* const* d_in, const int* in_sizes, int n_in,
                              void* d_out, int out_size)
{
    const float* x      = (const float*)d_in[0];
    const float* w_ih_f = (const float*)d_in[1];
    const float* w_hh_f = (const float*)d_in[2];
    const float* b_ih_f = (const float*)d_in[3];
    const float* b_hh_f = (const float*)d_in[4];
    const float* w_ih_b = (const float*)d_in[5];
    const float* w_hh_b = (const float*)d_in[6];
    const float* b_ih_b = (const float*)d_in[7];
    const float* b_hh_b = (const float*)d_in[8];
    float* out = (float*)d_out;

    dim3 gg(G3 / BN, M_ROWS / BM, 2);   // (6, 512, 2)
    gi_gemm<<<gg, 256>>>(x, w_ih_f, b_ih_f, w_ih_b, b_ih_b);

    gru_scan<<<128, 384>>>(w_hh_f, b_hh_f, w_hh_b, b_hh_b, out);
}